// round 1
// baseline (speedup 1.0000x reference)
#include <cuda_runtime.h>

#define BB 512
#define TT 4096
#define HH 32

__device__ __forceinline__ unsigned long long pk2(float lo, float hi) {
    unsigned long long r;
    asm("mov.b64 %0, {%1,%2};" : "=l"(r) : "f"(lo), "f"(hi));
    return r;
}
__device__ __forceinline__ void upk2(unsigned long long v, float& lo, float& hi) {
    asm("mov.b64 {%0,%1}, %2;" : "=f"(lo), "=f"(hi) : "l"(v));
}
__device__ __forceinline__ void fma2(unsigned long long& d, unsigned long long a, unsigned long long b) {
    asm("fma.rn.f32x2 %0, %1, %2, %0;" : "+l"(d) : "l"(a), "l"(b));
}
__device__ __forceinline__ unsigned long long add2(unsigned long long a, unsigned long long b) {
    unsigned long long r;
    asm("add.rn.f32x2 %0, %1, %2;" : "=l"(r) : "l"(a), "l"(b));
    return r;
}
// tanh(x) = 1 - 2/(1 + exp(2x)); ex2.approx/rcp.approx are ~1e-6 accurate and
// saturate correctly for large |x| (e -> inf -> r -> 0 -> 1; e -> 0 -> r -> 1 -> -1).
__device__ __forceinline__ float tanh_fast(float x) {
    float e, r;
    asm("ex2.approx.f32 %0, %1;" : "=f"(e) : "f"(x * 2.8853900817779268f)); // 2*log2(e)
    asm("rcp.approx.f32 %0, %1;" : "=f"(r) : "f"(e + 1.0f));
    return fmaf(-2.0f, r, 1.0f);
}

__global__ __launch_bounds__(128, 1)
void rnn_fused_kernel(const float* __restrict__ x,
                      const float* __restrict__ h0,
                      const float* __restrict__ W_ih,
                      const float* __restrict__ b_ih,
                      const float* __restrict__ W_hh,
                      const float* __restrict__ b_hh,
                      const float* __restrict__ W_out,
                      const float* __restrict__ b_out,
                      float* __restrict__ out,
                      int write_h) {
    // One warp per batch element. lane i owns h[i] and row i of W_hh.
    __shared__ __align__(16) float hs[4][2][32];  // [warp][ping-pong][H]

    const int wid  = threadIdx.x >> 5;
    const int lane = threadIdx.x & 31;
    const int b    = blockIdx.x * 4 + wid;

    // Load W_hh row (32 floats) as 16 packed f32x2 pairs.
    unsigned long long Wr[16];
    const float4* wp = reinterpret_cast<const float4*>(W_hh + lane * HH);
#pragma unroll
    for (int k = 0; k < 8; k++) {
        float4 v = wp[k];
        Wr[2 * k]     = pk2(v.x, v.y);
        Wr[2 * k + 1] = pk2(v.z, v.w);
    }
    const float wih  = W_ih[lane];                    // [H,1]
    const float bias = b_ih[lane] + b_hh[lane];
    const float wout = W_out[lane];                   // [1,H]
    const float bout = b_out[0];

    float h = h0[b * HH + lane];                      // [1,B,H]

    float* buf0 = hs[wid][0];
    float* buf1 = hs[wid][1];
    const float* xb = x + (long)b * TT;               // [B,T,1]
    float* ob       = out + (long)b * TT;             // outs [B,T,1]

    float xv   = xb[lane];                            // x for steps t0..t0+31
    float ybuf = 0.0f;

    for (int t0 = 0; t0 < TT; t0 += 32) {
        // Prefetch next 32 x values (off critical path).
        float xv_next = (t0 + 32 < TT) ? xb[t0 + 32 + lane] : 0.0f;

#pragma unroll
        for (int s = 0; s < 32; s++) {
            float xt = __shfl_sync(0xffffffffu, xv, s);
            float xp = fmaf(xt, wih, bias);           // x_t*W_ih + b_ih + b_hh

            // Publish h to this step's buffer (ping-pong removes the WAR
            // hazard; the single syncwarp orders STS -> LDS visibility).
            float* bw = (s & 1) ? buf1 : buf0;
            bw[lane] = h;
            __syncwarp();

            const ulonglong2* hp = reinterpret_cast<const ulonglong2*>(bw);
            unsigned long long a0 = pk2(xp, 0.0f);    // fold xp into accum 0
            unsigned long long a1 = 0ull, a2 = 0ull, a3 = 0ull;
#pragma unroll
            for (int k = 0; k < 8; k += 2) {
                ulonglong2 v0 = hp[k];                // h pairs 4k .. 4k+3
                ulonglong2 v1 = hp[k + 1];
                fma2(a0, Wr[2 * k],     v0.x);
                fma2(a1, Wr[2 * k + 1], v0.y);
                fma2(a2, Wr[2 * k + 2], v1.x);
                fma2(a3, Wr[2 * k + 3], v1.y);
            }
            unsigned long long s01 = add2(a0, a1);
            unsigned long long s23 = add2(a2, a3);
            unsigned long long ssu = add2(s01, s23);
            float lo, hi;
            upk2(ssu, lo, hi);
            h = tanh_fast(lo + hi);

            // Output projection (off the recurrence critical path).
            float y = wout * h;
            y += __shfl_xor_sync(0xffffffffu, y, 16);
            y += __shfl_xor_sync(0xffffffffu, y, 8);
            y += __shfl_xor_sync(0xffffffffu, y, 4);
            y += __shfl_xor_sync(0xffffffffu, y, 2);
            y += __shfl_xor_sync(0xffffffffu, y, 1);
            if (lane == s) ybuf = y + bout;
        }

        ob[t0 + lane] = ybuf;                         // coalesced 128B store
        xv = xv_next;
    }

    // Second output: final hidden state h_state [1,B,H], appended after outs.
    if (write_h) {
        out[(long)BB * TT + b * HH + lane] = h;
    }
}

extern "C" void kernel_launch(void* const* d_in, const int* in_sizes, int n_in,
                              void* d_out, int out_size) {
    const float* x     = (const float*)d_in[0];
    const float* h0    = (const float*)d_in[1];
    const float* W_ih  = (const float*)d_in[2];
    const float* b_ih  = (const float*)d_in[3];
    const float* W_hh  = (const float*)d_in[4];
    const float* b_hh  = (const float*)d_in[5];
    const float* W_out = (const float*)d_in[6];
    const float* b_out = (const float*)d_in[7];
    float* out = (float*)d_out;

    int write_h = (out_size >= BB * TT + BB * HH) ? 1 : 0;

    rnn_fused_kernel<<<BB / 4, 128>>>(x, h0, W_ih, b_ih, W_hh, b_hh,
                                      W_out, b_out, out, write_h);
}

// round 2
// speedup vs baseline: 1.0081x; 1.0081x over previous
#include <cuda_runtime.h>

#define BB 512
#define TT 4096
#define HH 32

static __device__ __forceinline__ unsigned long long pk2(float lo, float hi) {
    unsigned long long r;
    asm("mov.b64 %0, {%1,%2};" : "=l"(r) : "f"(lo), "f"(hi));
    return r;
}
static __device__ __forceinline__ void upk2(unsigned long long v, float& lo, float& hi) {
    asm("mov.b64 {%0,%1}, %2;" : "=f"(lo), "=f"(hi) : "l"(v));
}
static __device__ __forceinline__ void fma2(unsigned long long& d, unsigned long long a, unsigned long long b) {
    asm("fma.rn.f32x2 %0, %1, %2, %0;" : "+l"(d) : "l"(a), "l"(b));
}
static __device__ __forceinline__ unsigned long long add2(unsigned long long a, unsigned long long b) {
    unsigned long long r;
    asm("add.rn.f32x2 %0, %1, %2;" : "=l"(r) : "l"(a), "l"(b));
    return r;
}
static __device__ __forceinline__ unsigned int smem_u32(const void* p) {
    unsigned int a;
    asm("{ .reg .u64 t; cvta.to.shared.u64 t, %1; cvt.u32.u64 %0, t; }" : "=r"(a) : "l"(p));
    return a;
}

__global__ __launch_bounds__(128, 1)
void rnn_fused_kernel(const float* __restrict__ x,
                      const float* __restrict__ h0,
                      const float* __restrict__ W_ih,
                      const float* __restrict__ b_ih,
                      const float* __restrict__ W_hh,
                      const float* __restrict__ b_hh,
                      const float* __restrict__ W_out,
                      const float* __restrict__ b_out,
                      float* __restrict__ out,
                      int write_h) {
    // One warp per batch element; lane i owns h[i] and row i of W_hh.
    __shared__ __align__(16) float hs[4][32];

    const int wid  = threadIdx.x >> 5;
    const int lane = threadIdx.x & 31;
    const int b    = blockIdx.x * 4 + wid;

    const float SC = 2.8853900817779268f;  // 2*log2(e): pre-scale so tanh starts at ex2

    // W_hh row, pre-scaled, packed as f32x2 pairs.
    unsigned long long Wr[16];
    const float4* wp = reinterpret_cast<const float4*>(W_hh + lane * HH);
#pragma unroll
    for (int k = 0; k < 8; k++) {
        float4 v = wp[k];
        Wr[2 * k]     = pk2(v.x * SC, v.y * SC);
        Wr[2 * k + 1] = pk2(v.z * SC, v.w * SC);
    }
    // W_out vector (same in all lanes), packed.
    unsigned long long Wo[16];
    const float4* op = reinterpret_cast<const float4*>(W_out);
#pragma unroll
    for (int k = 0; k < 8; k++) {
        float4 v = op[k];
        Wo[2 * k]     = pk2(v.x, v.y);
        Wo[2 * k + 1] = pk2(v.z, v.w);
    }
    const float wihs  = W_ih[lane] * SC;
    const float biass = (b_ih[lane] + b_hh[lane]) * SC;
    const float bout  = b_out[0];

    float h = h0[b * HH + lane];

    float* buf = hs[wid];
    const unsigned int buf_st = smem_u32(buf) + lane * 4u;
    const ulonglong2* hp = reinterpret_cast<const ulonglong2*>(buf);

    const float* xb = x + (long)b * TT;
    float* ob       = out + (long)b * TT;

    float xv   = xb[lane];   // x for steps t0..t0+31
    float ybuf = 0.0f;

    for (int t0 = 0; t0 < TT; t0 += 32) {
        float xv_next = (t0 + 32 < TT) ? xb[t0 + 32 + lane] : 0.0f;

#pragma unroll 4
        for (int s = 0; s < 32; s++) {
            float xt = __shfl_sync(0xffffffffu, xv, s);
            float xp = fmaf(xt, wihs, biass);  // scaled input projection + bias

            // Publish h (warp-wide, in-order LSU; "memory" clobber pins ordering).
            asm volatile("st.shared.f32 [%0], %1;" :: "r"(buf_st), "f"(h) : "memory");

            ulonglong2 q0 = hp[0], q1 = hp[1], q2 = hp[2], q3 = hp[3];
            ulonglong2 q4 = hp[4], q5 = hp[5], q6 = hp[6], q7 = hp[7];

            // Recurrence dot: z' = SC*(W_hh.h + bias + x*wih), 4 accumulators.
            unsigned long long a0 = pk2(xp, 0.0f), a1 = 0ull, a2 = 0ull, a3 = 0ull;
            fma2(a0, Wr[0],  q0.x); fma2(a1, Wr[1],  q0.y);
            fma2(a2, Wr[2],  q1.x); fma2(a3, Wr[3],  q1.y);
            fma2(a0, Wr[4],  q2.x); fma2(a1, Wr[5],  q2.y);
            fma2(a2, Wr[6],  q3.x); fma2(a3, Wr[7],  q3.y);
            fma2(a0, Wr[8],  q4.x); fma2(a1, Wr[9],  q4.y);
            fma2(a2, Wr[10], q5.x); fma2(a3, Wr[11], q5.y);
            fma2(a0, Wr[12], q6.x); fma2(a1, Wr[13], q6.y);
            fma2(a2, Wr[14], q7.x); fma2(a3, Wr[15], q7.y);
            unsigned long long ss = add2(add2(a0, a1), add2(a2, a3));
            float lo, hi; upk2(ss, lo, hi);
            float zp = lo + hi;  // = 2*log2(e) * preactivation
            float e, r;
            asm("ex2.approx.f32 %0, %1;" : "=f"(e) : "f"(zp));
            asm("rcp.approx.f32 %0, %1;" : "=f"(r) : "f"(e + 1.0f));
            h = fmaf(-2.0f, r, 1.0f);  // tanh = 1 - 2/(1+e^{2z})

            // Output for the PREVIOUS step: y_{t-1} = wout . q + bout.
            // Every lane computes it redundantly from the loaded vector —
            // zero serial cross-lane dependency on the recurrence chain.
            unsigned long long y0 = pk2(bout, 0.0f), y1 = 0ull, y2 = 0ull, y3 = 0ull;
            fma2(y0, Wo[0],  q0.x); fma2(y1, Wo[1],  q0.y);
            fma2(y2, Wo[2],  q1.x); fma2(y3, Wo[3],  q1.y);
            fma2(y0, Wo[4],  q2.x); fma2(y1, Wo[5],  q2.y);
            fma2(y2, Wo[6],  q3.x); fma2(y3, Wo[7],  q3.y);
            fma2(y0, Wo[8],  q4.x); fma2(y1, Wo[9],  q4.y);
            fma2(y2, Wo[10], q5.x); fma2(y3, Wo[11], q5.y);
            fma2(y0, Wo[12], q6.x); fma2(y1, Wo[13], q6.y);
            fma2(y2, Wo[14], q7.x); fma2(y3, Wo[15], q7.y);
            unsigned long long ys = add2(add2(y0, y1), add2(y2, y3));
            float ylo, yhi; upk2(ys, ylo, yhi);
            float yv = ylo + yhi;

            // y_{t-1} belongs to lane (t-1)&31 of ybuf. At (t0=0,s=0) this
            // writes garbage into lane 31, but it is overwritten at (32,0)
            // before the first store.
            if (lane == ((s + 31) & 31)) ybuf = yv;
            // Completed previous block -> coalesced 128B store.
            if (s == 0 && t0 > 0) ob[t0 - 32 + lane] = ybuf;
        }
        xv = xv_next;
    }

    // Tail: y_{TT-1} from the final h.
    asm volatile("st.shared.f32 [%0], %1;" :: "r"(buf_st), "f"(h) : "memory");
    {
        ulonglong2 q0 = hp[0], q1 = hp[1], q2 = hp[2], q3 = hp[3];
        ulonglong2 q4 = hp[4], q5 = hp[5], q6 = hp[6], q7 = hp[7];
        unsigned long long y0 = pk2(bout, 0.0f), y1 = 0ull, y2 = 0ull, y3 = 0ull;
        fma2(y0, Wo[0],  q0.x); fma2(y1, Wo[1],  q0.y);
        fma2(y2, Wo[2],  q1.x); fma2(y3, Wo[3],  q1.y);
        fma2(y0, Wo[4],  q2.x); fma2(y1, Wo[5],  q2.y);
        fma2(y2, Wo[6],  q3.x); fma2(y3, Wo[7],  q3.y);
        fma2(y0, Wo[8],  q4.x); fma2(y1, Wo[9],  q4.y);
        fma2(y2, Wo[10], q5.x); fma2(y3, Wo[11], q5.y);
        fma2(y0, Wo[12], q6.x); fma2(y1, Wo[13], q6.y);
        fma2(y2, Wo[14], q7.x); fma2(y3, Wo[15], q7.y);
        unsigned long long ys = add2(add2(y0, y1), add2(y2, y3));
        float ylo, yhi; upk2(ys, ylo, yhi);
        if (lane == 31) ybuf = ylo + yhi;
    }
    ob[TT - 32 + lane] = ybuf;

    // Final hidden state h_state [1,B,H], appended after outs.
    if (write_h) {
        out[(long)BB * TT + b * HH + lane] = h;
    }
}

extern "C" void kernel_launch(void* const* d_in, const int* in_sizes, int n_in,
                              void* d_out, int out_size) {
    const float* x     = (const float*)d_in[0];
    const float* h0    = (const float*)d_in[1];
    const float* W_ih  = (const float*)d_in[2];
    const float* b_ih  = (const float*)d_in[3];
    const float* W_hh  = (const float*)d_in[4];
    const float* b_hh  = (const float*)d_in[5];
    const float* W_out = (const float*)d_in[6];
    const float* b_out = (const float*)d_in[7];
    float* out = (float*)d_out;

    int write_h = (out_size >= BB * TT + BB * HH) ? 1 : 0;

    rnn_fused_kernel<<<BB / 4, 128>>>(x, h0, W_ih, b_ih, W_hh, b_hh,
                                      W_out, b_out, out, write_h);
}

// round 3
// speedup vs baseline: 1.7367x; 1.7227x over previous
#include <cuda_runtime.h>

#define BB 512
#define TT 4096
#define HH 32
#define NBLK (TT / 32)   // 128 blocks of 32 timesteps
#define RSTR 36          // padded row stride in floats (144B, 16B-aligned)

static __device__ __forceinline__ unsigned long long pk2(float lo, float hi) {
    unsigned long long r;
    asm("mov.b64 %0, {%1,%2};" : "=l"(r) : "f"(lo), "f"(hi));
    return r;
}
static __device__ __forceinline__ void upk2(unsigned long long v, float& lo, float& hi) {
    asm("mov.b64 {%0,%1}, %2;" : "=f"(lo), "=f"(hi) : "l"(v));
}
static __device__ __forceinline__ void fma2(unsigned long long& d, unsigned long long a, unsigned long long b) {
    asm("fma.rn.f32x2 %0, %1, %2, %0;" : "+l"(d) : "l"(a), "l"(b));
}
static __device__ __forceinline__ unsigned long long add2(unsigned long long a, unsigned long long b) {
    unsigned long long r;
    asm("add.rn.f32x2 %0, %1, %2;" : "=l"(r) : "l"(a), "l"(b));
    return r;
}
static __device__ __forceinline__ unsigned int smem_u32(const void* p) {
    unsigned int a;
    asm("{ .reg .u64 t; cvta.to.shared.u64 t, %1; cvt.u32.u64 %0, t; }" : "=r"(a) : "l"(p));
    return a;
}

// SMEM rings: [double-buffer][chain-pair][33 h-vectors][padded 36 floats]
__shared__ __align__(16) float g_bufs[2][4][33][RSTR];

__global__ __launch_bounds__(256, 1)
void rnn_fused_kernel(const float* __restrict__ x,
                      const float* __restrict__ h0,
                      const float* __restrict__ W_ih,
                      const float* __restrict__ b_ih,
                      const float* __restrict__ W_hh,
                      const float* __restrict__ b_hh,
                      const float* __restrict__ W_out,
                      const float* __restrict__ b_out,
                      float* __restrict__ out,
                      int write_h) {
    const int wid  = threadIdx.x >> 5;
    const int lane = threadIdx.x & 31;
    const int p    = wid & 3;                 // chain-pair id 0..3
    const int b    = blockIdx.x * 4 + p;      // batch chain

    if (wid >= 4) {
        // ───────────── MAIN (recurrence) warp: wid 4..7, hi arbiter priority ─────────────
        unsigned long long Wr[16];
        const float4* wp = reinterpret_cast<const float4*>(W_hh + lane * HH);
#pragma unroll
        for (int k = 0; k < 8; k++) {
            float4 v = wp[k];
            Wr[2 * k]     = pk2(v.x, v.y);
            Wr[2 * k + 1] = pk2(v.z, v.w);
        }
        const float wih  = W_ih[lane];
        const float bias = b_ih[lane] + b_hh[lane];

        float h = h0[b * HH + lane];
        const float* xb = x + (long)b * TT;
        float xv = xb[lane];

        for (int k = 0; k < NBLK; k++) {
            float xv_next = (k + 1 < NBLK) ? xb[k * 32 + 32 + lane] : 0.0f;

            float* base = &g_bufs[k & 1][p][0][0];
            const unsigned int bs = smem_u32(base) + lane * 4u;

#pragma unroll
            for (int s = 0; s < 32; s++) {
                float xt = __shfl_sync(0xffffffffu, xv, s);
                float xp = fmaf(xt, wih, bias);

                // Publish entering state h_{t0+s} into ring row s.
                asm volatile("st.shared.f32 [%0], %1;"
                             :: "r"(bs + s * (RSTR * 4)), "f"(h) : "memory");

                const ulonglong2* hp =
                    reinterpret_cast<const ulonglong2*>(base + s * RSTR);
                ulonglong2 q0 = hp[0], q1 = hp[1], q2 = hp[2], q3 = hp[3];
                ulonglong2 q4 = hp[4], q5 = hp[5], q6 = hp[6], q7 = hp[7];

                unsigned long long a0 = pk2(xp, 0.0f), a1 = 0ull;
                fma2(a0, Wr[0],  q0.x); fma2(a1, Wr[1],  q0.y);
                fma2(a0, Wr[2],  q1.x); fma2(a1, Wr[3],  q1.y);
                fma2(a0, Wr[4],  q2.x); fma2(a1, Wr[5],  q2.y);
                fma2(a0, Wr[6],  q3.x); fma2(a1, Wr[7],  q3.y);
                fma2(a0, Wr[8],  q4.x); fma2(a1, Wr[9],  q4.y);
                fma2(a0, Wr[10], q5.x); fma2(a1, Wr[11], q5.y);
                fma2(a0, Wr[12], q6.x); fma2(a1, Wr[13], q6.y);
                fma2(a0, Wr[14], q7.x); fma2(a1, Wr[15], q7.y);
                unsigned long long ss = add2(a0, a1);
                float lo, hi; upk2(ss, lo, hi);
                float z = lo + hi;
                asm("tanh.approx.f32 %0, %1;" : "=f"(h) : "f"(z));  // MUFU.TANH
            }
            // Row 32: state after the last step of this block (for y_{t0+31}).
            asm volatile("st.shared.f32 [%0], %1;"
                         :: "r"(bs + 32 * (RSTR * 4)), "f"(h) : "memory");
            // Hand block k to the helper; also confirms helper is done with
            // this buffer's previous contents (2-deep ping-pong).
            asm volatile("bar.sync %0, %1;" :: "r"(p), "r"(64) : "memory");

            xv = xv_next;
        }

        if (write_h) {
            out[(long)BB * TT + b * HH + lane] = h;   // h_state [1,B,H]
        }
    } else {
        // ───────────── HELPER (output projection) warp: wid 0..3 ─────────────
        unsigned long long Wo[16];
        const float4* op = reinterpret_cast<const float4*>(W_out);
#pragma unroll
        for (int k = 0; k < 8; k++) {
            float4 v = op[k];
            Wo[2 * k]     = pk2(v.x, v.y);
            Wo[2 * k + 1] = pk2(v.z, v.w);
        }
        const float bout = b_out[0];
        float* ob = out + (long)b * TT;

        for (int k = 0; k < NBLK; k++) {
            asm volatile("bar.sync %0, %1;" :: "r"(p), "r"(64) : "memory");

            // Lane s computes y_{t0+s} = W_out . h_{t0+s+1} + b_out
            // from ring row s+1 (rows 1..32). 16B-aligned, 4-way conflicts: fine
            // off the critical path.
            const ulonglong2* rp =
                reinterpret_cast<const ulonglong2*>(&g_bufs[k & 1][p][lane + 1][0]);
            ulonglong2 q0 = rp[0], q1 = rp[1], q2 = rp[2], q3 = rp[3];
            ulonglong2 q4 = rp[4], q5 = rp[5], q6 = rp[6], q7 = rp[7];

            unsigned long long y0 = pk2(bout, 0.0f), y1 = 0ull;
            fma2(y0, Wo[0],  q0.x); fma2(y1, Wo[1],  q0.y);
            fma2(y0, Wo[2],  q1.x); fma2(y1, Wo[3],  q1.y);
            fma2(y0, Wo[4],  q2.x); fma2(y1, Wo[5],  q2.y);
            fma2(y0, Wo[6],  q3.x); fma2(y1, Wo[7],  q3.y);
            fma2(y0, Wo[8],  q4.x); fma2(y1, Wo[9],  q4.y);
            fma2(y0, Wo[10], q5.x); fma2(y1, Wo[11], q5.y);
            fma2(y0, Wo[12], q6.x); fma2(y1, Wo[13], q6.y);
            fma2(y0, Wo[14], q7.x); fma2(y1, Wo[15], q7.y);
            unsigned long long ys = add2(y0, y1);
            float ylo, yhi; upk2(ys, ylo, yhi);

            ob[k * 32 + lane] = ylo + yhi;   // coalesced 128B store
        }
    }
}

extern "C" void kernel_launch(void* const* d_in, const int* in_sizes, int n_in,
                              void* d_out, int out_size) {
    const float* x     = (const float*)d_in[0];
    const float* h0    = (const float*)d_in[1];
    const float* W_ih  = (const float*)d_in[2];
    const float* b_ih  = (const float*)d_in[3];
    const float* W_hh  = (const float*)d_in[4];
    const float* b_hh  = (const float*)d_in[5];
    const float* W_out = (const float*)d_in[6];
    const float* b_out = (const float*)d_in[7];
    float* out = (float*)d_out;

    int write_h = (out_size >= BB * TT + BB * HH) ? 1 : 0;

    rnn_fused_kernel<<<BB / 4, 256>>>(x, h0, W_ih, b_ih, W_hh, b_hh,
                                      W_out, b_out, out, write_h);
}